// round 10
// baseline (speedup 1.0000x reference)
#include <cuda_runtime.h>
#include <cuda_pipeline.h>
#include <math_constants.h>

// Problem constants (NB, LQ, LK, DK, DV = 16, 384, 384, 64, 64)
#define NB 16
#define LQ 384
#define LK 384
#define DK 64
#define DV 64
#define INV_TEMP 0.125f  // 1 / TEMPERATURE, TEMPERATURE = 8.0
#define PF 5             // prefetched phase-C iterations (4 KB each, 20 KB smem)

// Scratch for attn probabilities in case the harness output only holds `output`.
__device__ float g_attn_scratch[NB * LQ * LK];

// ---------------------------------------------------------------------------
// Fused kernel, one block per (n,q), 256 threads, occ 8 (R8 geometry, proven).
//
// R8 measured DRAM=76% because phases A+B (attn prologue, no DRAM traffic)
// run in lockstep across the 8 resident blocks at each wave start, idling
// DRAM ~2.5us per wave. Fix: before phase A, issue the first PF=5 streaming
// iterations of rel_pos_v as cp.async into smem (20 KB). These proceed in the
// background during A+B (160 KB in flight per SM ~= 3.5us of DRAM time at the
// per-SM share), closing the idle window. Phase C consumes the 5 smem iters
// (each thread reads only its own prefetched value -> pipeline wait suffices)
// then streams the remaining 19 from gmem as before.
//
// Phase A: half-warp-per-K-row dot (512B-coalesced, L2-hot K), shfl folds.
// Phase B: block softmax, probs -> smem + attn output.
// Phase C: rel_pos_v stream + block reduction (unchanged math).
// ---------------------------------------------------------------------------
__global__ __launch_bounds__(256, 8)
void fused_kernel(const float* __restrict__ q,
                  const float* __restrict__ k,
                  const float* __restrict__ rpv,
                  float* __restrict__ out,
                  float* __restrict__ attn_ext)
{
    __shared__ float4 sq4[DK / 4];   // q row, 256 B
    __shared__ float  sa[LK];        // scores -> probs, 1.5 KB
    __shared__ float4 rbuf[256];     // reduction buffer, 4 KB
    __shared__ float  red[16];       // block-reduction partials
    __shared__ float4 pv4[PF][256];  // cp.async prefetch buffer, 20 KB

    float* attn = attn_ext ? attn_ext : g_attn_scratch;

    const int nq   = blockIdx.x;           // n*LQ + q
    const int n    = nq / LQ;
    const int tid  = threadIdx.x;
    const int lane = tid & 31;
    const int warp = tid >> 5;

    // Streaming-thread coordinates (used by prefetch now and phase C later).
    const int cd4 = tid & 15;   // float4 column (d = 4*cd4 .. 4*cd4+3)
    const int ckk = tid >> 4;   // k-slice start (k = ckk, ckk+16, ...)
    const float4* base = reinterpret_cast<const float4*>(
        rpv + (size_t)nq * LK * DV);

    // ---- Prefetch: first PF phase-C iterations, async, before any compute.
#pragma unroll
    for (int i = 0; i < PF; i++) {
        const int kidx = ckk + i * 16;
        __pipeline_memcpy_async(&pv4[i][tid],
                                &base[kidx * (DV / 4) + cd4],
                                sizeof(float4));
    }
    __pipeline_commit();

    // ---- Phase A: attn scores for this (n,q) row. ----
    if (tid < DK / 4) {
        sq4[tid] = reinterpret_cast<const float4*>(q + (size_t)nq * DK)[tid];
    }
    __syncthreads();

    {
        const int half = tid >> 4;         // 0..15: half-warp id
        const int d4   = tid & 15;         // float4 column within the K row
        const float4 qv = sq4[d4];

        const float4* kbase = reinterpret_cast<const float4*>(
            k + (size_t)n * LK * DK);

#pragma unroll
        for (int i = 0; i < LK / 16; i++) {          // 24 passes
            const int krow = half + 16 * i;
            // Warp covers 512 contiguous bytes (2 K-rows). L2-hot.
            const float4 kv = kbase[krow * (DK / 4) + d4];
            float p = qv.x * kv.x + qv.y * kv.y + qv.z * kv.z + qv.w * kv.w;
            p += __shfl_xor_sync(0xFFFFFFFFu, p, 8);
            p += __shfl_xor_sync(0xFFFFFFFFu, p, 4);
            p += __shfl_xor_sync(0xFFFFFFFFu, p, 2);
            p += __shfl_xor_sync(0xFFFFFFFFu, p, 1);
            if (d4 == 0) sa[krow] = p * INV_TEMP;
        }
    }
    __syncthreads();

    // ---- Phase B: softmax over sa[0..383] with 256 threads. ----
    {
        const float v1 = sa[tid];
        const float v2 = (tid < LK - 256) ? sa[tid + 256] : -CUDART_INF_F;

        // Block max.
        float m = fmaxf(v1, v2);
#pragma unroll
        for (int s = 16; s > 0; s >>= 1)
            m = fmaxf(m, __shfl_xor_sync(0xFFFFFFFFu, m, s));
        if (lane == 0) red[warp] = m;
        __syncthreads();
        if (tid < 32) {
            float t = (lane < 8) ? red[lane] : -CUDART_INF_F;
#pragma unroll
            for (int s = 4; s > 0; s >>= 1)
                t = fmaxf(t, __shfl_xor_sync(0xFFFFFFFFu, t, s));
            if (lane == 0) red[0] = t;
        }
        __syncthreads();
        const float mm = red[0];

        // exp + block sum.
        const float e1 = __expf(v1 - mm);
        const float e2 = (tid < LK - 256) ? __expf(v2 - mm) : 0.0f;
        float s = e1 + e2;
#pragma unroll
        for (int sh = 16; sh > 0; sh >>= 1)
            s += __shfl_xor_sync(0xFFFFFFFFu, s, sh);
        if (lane == 0) red[8 + warp] = s;
        __syncthreads();
        if (tid < 32) {
            float t = (lane < 8) ? red[8 + lane] : 0.0f;
#pragma unroll
            for (int sh = 4; sh > 0; sh >>= 1)
                t += __shfl_xor_sync(0xFFFFFFFFu, t, sh);
            if (lane == 0) red[8] = t;
        }
        __syncthreads();
        const float inv = 1.0f / red[8];

        // Probs to smem + attn output (coalesced).
        float* arow = attn + (size_t)nq * LK;
        const float p1 = e1 * inv;
        sa[tid]   = p1;
        arow[tid] = p1;
        if (tid < LK - 256) {
            const float p2 = e2 * inv;
            sa[tid + 256]   = p2;
            arow[tid + 256] = p2;
        }
    }
    __syncthreads();   // probs visible to all threads for phase C

    // ---- Phase C: stream rel_pos_v; first PF iters from the prefetch. ----
    float4 acc = make_float4(0.f, 0.f, 0.f, 0.f);

    __pipeline_wait_prior(0);   // own-thread data only; no block sync needed
#pragma unroll
    for (int i = 0; i < PF; i++) {
        const int kidx = ckk + i * 16;
        const float  a = sa[kidx];
        const float4 v = pv4[i][tid];
        acc.x += a * v.x;
        acc.y += a * v.y;
        acc.z += a * v.z;
        acc.w += a * v.w;
    }

#pragma unroll
    for (int i = PF; i < LK / 16; i++) {          // remaining 19 iterations
        const int kidx = ckk + i * 16;
        const float  a = sa[kidx];
        const float4 v = base[kidx * (DV / 4) + cd4];
        acc.x += a * v.x;
        acc.y += a * v.y;
        acc.z += a * v.z;
        acc.w += a * v.w;
    }

    rbuf[tid] = acc;
    __syncthreads();

#pragma unroll
    for (int s = 128; s >= 16; s >>= 1) {
        if (tid < s) {
            float4 a = rbuf[tid];
            float4 b = rbuf[tid + s];
            a.x += b.x; a.y += b.y; a.z += b.z; a.w += b.w;
            rbuf[tid] = a;
        }
        __syncthreads();
    }

    if (tid < DV) {
        out[(size_t)nq * DV + tid] = reinterpret_cast<const float*>(rbuf)[tid];
    }
}

// ---------------------------------------------------------------------------
// Launch. Inputs (metadata order) = q, k, v, rel_pos, rel_pos_v.
// v and rel_pos are unused by the reference — never touched.
// Output layout: [output (NB*LQ*DV) | attn (NB*LQ*LK)] when out_size covers
// both (branch taken and passing since R3); otherwise attn -> scratch.
// ---------------------------------------------------------------------------
extern "C" void kernel_launch(void* const* d_in, const int* in_sizes, int n_in,
                              void* d_out, int out_size)
{
    const float* q   = (const float*)d_in[0];
    const float* k   = (const float*)d_in[1];
    const float* rpv = (const float*)d_in[4];
    float* out = (float*)d_out;

    const long long out_elems  = (long long)NB * LQ * DV;   // 393216
    const long long attn_elems = (long long)NB * LQ * LK;   // 2359296

    float* attn_ext = nullptr;  // null -> kernel falls back to g_attn_scratch
    if ((long long)out_size >= out_elems + attn_elems) {
        attn_ext = out + out_elems;
    }

    fused_kernel<<<NB * LQ, 256>>>(q, k, rpv, out, attn_ext);
}